// round 11
// baseline (speedup 1.0000x reference)
#include <cuda_runtime.h>
#include <cuda_bf16.h>
#include <cstdint>
#include <cstddef>

namespace {
constexpr int Bn   = 1024;
constexpr int BnP  = 1032;   // padded rows (zero tail)
constexpr int Tn   = 512;
constexpr int Hn   = 64;
constexpr int NB   = 7;      // real rows per block -> grid 147 (N=8 with pad row)
constexpr int GRID = 147;
constexpr int NT   = 1024;   // 16 consumer warps + 16 producer warps
}

// Inter-layer activations, [t][b][64], f32, rows >=1024 stay zero.
__device__ float g_seq0[(size_t)Tn * BnP * 64];
__device__ float g_seq1[(size_t)Tn * BnP * 64];
// Layer-0 input transposed+padded: [t][b][64] (cols 22..63 zero)
__device__ float g_x64[(size_t)Tn * BnP * 64];

__device__ __forceinline__ float htanh(float x) {   // HW MUFU.TANH
    float y;
    asm("tanh.approx.f32 %0, %1;" : "=f"(y) : "f"(x));
    return y;
}
__device__ __forceinline__ float sigm(float x) {    // 0.5 + 0.5*tanh(x/2)
    return fmaf(htanh(0.5f * x), 0.5f, 0.5f);
}
__device__ __forceinline__ uint32_t bf2(float a, float b) {
    __nv_bfloat162 t = __floats2bfloat162_rn(a, b);
    return *reinterpret_cast<uint32_t*>(&t);
}
__device__ __forceinline__ float bfr(float v) {
    return __bfloat162float(__float2bfloat16(v));
}

// m16n8k16 bf16 MMA, fp32 accumulate (sm_80 baseline PTX).
__device__ __forceinline__ void hmma(float& d0, float& d1, float& d2, float& d3,
                                     uint32_t a0, uint32_t a1, uint32_t a2, uint32_t a3,
                                     uint32_t b0, uint32_t b1) {
    asm volatile(
        "mma.sync.aligned.m16n8k16.row.col.f32.bf16.bf16.f32 "
        "{%0,%1,%2,%3}, {%4,%5,%6,%7}, {%8,%9}, {%0,%1,%2,%3};"
        : "+f"(d0), "+f"(d1), "+f"(d2), "+f"(d3)
        : "r"(a0), "r"(a1), "r"(a2), "r"(a3), "r"(b0), "r"(b1));
}

// Transpose x[b][22][t] -> g_x64[t][b][0..63] (cols 22..63 zero).
__global__ void __launch_bounds__(256)
transpose_x_k(const float* __restrict__ x)
{
    const int b  = blockIdx.x >> 3;
    const int t0 = (blockIdx.x & 7) * 64;
    __shared__ float tile[22][65];
    for (int e = threadIdx.x; e < 22 * 64; e += 256) {
        int i = e / 64, tt = e - i * 64;
        tile[i][tt] = x[(size_t)b * (22 * Tn) + i * Tn + t0 + tt];
    }
    __syncthreads();
    for (int e = threadIdx.x; e < 64 * 64; e += 256) {
        int tt = e >> 6, i = e & 63;
        g_x64[((size_t)(t0 + tt) * BnP + b) * 64 + i] = (i < 22) ? tile[i][tt] : 0.f;
    }
}

// Warp-specialized LSTM layer on HMMA tensor cores.
//   warps 0-15  (consumers): W_h·h(t-1) + gx(t) -> combine (warp-local via
//                            row-permuted weights + shfl.bfly(16))
//   warps 16-31 (producers): gx(t+1) = W_x·x(t+1)+bias into parity smem buf,
//                            x staging, h(t-1) flush to global.
// B tile bf16 hi/lo, row stride 264 (u32 132 -> conflict-free frags):
//   [0,64) x slot0 | [64,128) x slot1 | [128,192) h slot0 | [192,256) h slot1
// All slots parity double-buffered -> ONE __syncthreads per step, race-free.
template<int LAYER>
__global__ void __launch_bounds__(NT, 1)
lstm_hmma_k(const float* __restrict__ w_ih, const float* __restrict__ w_hh,
            const float* __restrict__ b_ih, const float* __restrict__ b_hh,
            const float* __restrict__ w_fc, const float* __restrict__ b_fc,
            float* __restrict__ out_fc)
{
    constexpr bool LAST = (LAYER == 2);
    constexpr int  DIN  = (LAYER == 0) ? 22 : 64;
    constexpr int  XCH  = (LAYER == 0) ? 2 : 4;     // x k-chunks (cols >=32 zero for L0)
    const float* xin  = (LAYER == 0) ? g_x64 : (LAYER == 1 ? g_seq0 : g_seq1);
    float*       outs = (LAYER == 0) ? g_seq0 : (LAYER == 1 ? g_seq1 : nullptr);

    __shared__ __align__(16) __nv_bfloat16 in_hi[8][264];
    __shared__ __align__(16) __nv_bfloat16 in_lo[8][264];
    __shared__ float4 gx[2][16][32];     // parity x-projection, consumer frag layout
    __shared__ float h_out[2][8][68];    // parity f32 h staging

    const int tid  = threadIdx.x;
    const int lane = tid & 31;
    const int wid  = tid >> 5;
    const bool prod = (wid >= 16);
    const int cw   = prod ? (wid - 16) : wid;    // role-local warp 0..15
    const int gid  = lane >> 2;                  // 0..7
    const int qid  = lane & 3;                   // 0..3
    const int b0   = blockIdx.x * NB;
    const int nrows = (Bn - b0 < NB) ? (Bn - b0) : NB;

    // permuted weight rows (identical mapping for producer & consumer warp cw)
    const int cell = 4 * cw + (gid & 3);
    const int m0 = ((gid >> 2) ? 64 : 0)    + cell;   // i or f row
    const int m1 = ((gid >> 2) ? 192 : 128) + cell;   // g or o row

    // ---- role-specific weight fragments (hi + lo bf16 split) ----
    uint32_t whi[4][4], wlo[4][4];
    {
        auto pair = [&](float p0, float p1, uint32_t& hi, uint32_t& lo) {
            float h0 = bfr(p0), h1 = bfr(p1);
            hi = bf2(h0, h1);
            lo = bf2(p0 - h0, p1 - h1);
        };
        if (prod) {
            auto wx = [&](int m, int k) -> float {
                return (k < DIN) ? w_ih[m * DIN + k] : 0.f;
            };
#pragma unroll
            for (int kc = 0; kc < XCH; kc++) {
                const int k0 = kc * 16 + qid * 2, k1 = k0 + 8;
                pair(wx(m0, k0), wx(m0, k0 + 1), whi[kc][0], wlo[kc][0]);
                pair(wx(m1, k0), wx(m1, k0 + 1), whi[kc][1], wlo[kc][1]);
                pair(wx(m0, k1), wx(m0, k1 + 1), whi[kc][2], wlo[kc][2]);
                pair(wx(m1, k1), wx(m1, k1 + 1), whi[kc][3], wlo[kc][3]);
            }
        } else {
#pragma unroll
            for (int kc = 0; kc < 4; kc++) {
                const int k0 = kc * 16 + qid * 2, k1 = k0 + 8;
                pair(w_hh[m0 * 64 + k0], w_hh[m0 * 64 + k0 + 1], whi[kc][0], wlo[kc][0]);
                pair(w_hh[m1 * 64 + k0], w_hh[m1 * 64 + k0 + 1], whi[kc][1], wlo[kc][1]);
                pair(w_hh[m0 * 64 + k1], w_hh[m0 * 64 + k1 + 1], whi[kc][2], wlo[kc][2]);
                pair(w_hh[m1 * 64 + k1], w_hh[m1 * 64 + k1 + 1], whi[kc][3], wlo[kc][3]);
            }
        }
    }
    const float biasA = prod ? (b_ih[m0] + b_hh[m0]) : 0.f;
    const float biasB = prod ? (b_ih[m1] + b_hh[m1]) : 0.f;

    // consumer combine identities
    const bool sideA = (lane < 16);
    const int  r0 = 2 * qid, r1 = 2 * qid + 1;
    float cst0 = 0.f, cst1 = 0.f;

    // producer staging identity (coalesced)
    const int ptid = tid & 511;
    const int sr = ptid >> 6, sc = ptid & 63;

    // ---- zero B tiles ----
    for (int e = tid; e < 8 * 264; e += NT) {
        (&in_hi[0][0])[e] = __float2bfloat16(0.f);
        (&in_lo[0][0])[e] = __float2bfloat16(0.f);
    }
    __syncthreads();
    if (prod) {   // stage x(0) -> x slot0, x(1) -> x slot1
        float v0 = xin[((size_t)0 * BnP + b0 + sr) * 64 + sc];
        float h0 = bfr(v0);
        in_hi[sr][sc] = __float2bfloat16(h0);
        in_lo[sr][sc] = __float2bfloat16(v0 - h0);
        float v1 = (Tn > 1) ? xin[((size_t)1 * BnP + b0 + sr) * 64 + sc] : 0.f;
        float h1 = bfr(v1);
        in_hi[sr][64 + sc] = __float2bfloat16(h1);
        in_lo[sr][64 + sc] = __float2bfloat16(v1 - h1);
    }
    __syncthreads();

    const uint32_t* rowH = reinterpret_cast<const uint32_t*>(&in_hi[gid][0]) + qid;
    const uint32_t* rowL = reinterpret_cast<const uint32_t*>(&in_lo[gid][0]) + qid;

    // producer: xproj(slot) -> float4 (bias folded), 3-term bf16 split
    auto xproj = [&](int slot) -> float4 {
        float d0 = biasA, d1 = biasA, d2 = biasB, d3 = biasB;
        float e0 = 0.f, e1 = 0.f, e2 = 0.f, e3 = 0.f;
        float f0 = 0.f, f1 = 0.f, f2 = 0.f, f3 = 0.f;
        const int wb = 32 * slot;
#pragma unroll
        for (int kc = 0; kc < XCH; kc++) {
            const uint32_t bh0 = rowH[wb + kc * 8];
            const uint32_t bh1 = rowH[wb + kc * 8 + 4];
            const uint32_t bl0 = rowL[wb + kc * 8];
            const uint32_t bl1 = rowL[wb + kc * 8 + 4];
            hmma(d0, d1, d2, d3, whi[kc][0], whi[kc][1], whi[kc][2], whi[kc][3], bh0, bh1);
            hmma(e0, e1, e2, e3, whi[kc][0], whi[kc][1], whi[kc][2], whi[kc][3], bl0, bl1);
            hmma(f0, f1, f2, f3, wlo[kc][0], wlo[kc][1], wlo[kc][2], wlo[kc][3], bh0, bh1);
        }
        return make_float4(d0 + e0 + f0, d1 + e1 + f1, d2 + e2 + f2, d3 + e3 + f3);
    };

    float xreg = 0.f;
    if (prod) {
        gx[0][cw][lane] = xproj(0);      // gx(0) ready before loop
        if (Tn > 2) xreg = xin[((size_t)2 * BnP + b0 + sr) * 64 + sc];
    }

    for (int t = 0; t < Tn; t++) {
        __syncthreads();   // gx(t), h(t-1) slot, x slots, h_out(t-1) all ready

        if (!prod) {
            // ---- consumer: W_h · h(t-1) from h slot (t+1)&1, init = gx(t) ----
            const float4 g4 = gx[t & 1][cw][lane];
            float d0 = g4.x, d1 = g4.y, d2 = g4.z, d3 = g4.w;
            float e0 = 0.f, e1 = 0.f, e2 = 0.f, e3 = 0.f;
            float f0 = 0.f, f1 = 0.f, f2 = 0.f, f3 = 0.f;
            const int hb = 64 + 32 * ((t + 1) & 1);
#pragma unroll
            for (int kc = 0; kc < 4; kc++) {
                const uint32_t bh0 = rowH[hb + kc * 8];
                const uint32_t bh1 = rowH[hb + kc * 8 + 4];
                const uint32_t bl0 = rowL[hb + kc * 8];
                const uint32_t bl1 = rowL[hb + kc * 8 + 4];
                hmma(d0, d1, d2, d3, whi[kc][0], whi[kc][1], whi[kc][2], whi[kc][3], bh0, bh1);
                hmma(e0, e1, e2, e3, whi[kc][0], whi[kc][1], whi[kc][2], whi[kc][3], bl0, bl1);
                hmma(f0, f1, f2, f3, wlo[kc][0], wlo[kc][1], wlo[kc][2], wlo[kc][3], bh0, bh1);
            }
            d0 += e0 + f0; d1 += e1 + f1; d2 += e2 + f2; d3 += e3 + f3;

            // warp-local gate gather: bfly(16) swaps (i,g)<->(f,o)
            const float p0 = __shfl_xor_sync(0xffffffffu, d0, 16);
            const float p1 = __shfl_xor_sync(0xffffffffu, d1, 16);
            const float p2 = __shfl_xor_sync(0xffffffffu, d2, 16);
            const float p3 = __shfl_xor_sync(0xffffffffu, d3, 16);
            const float gi0 = sideA ? d0 : p0, gf0 = sideA ? p0 : d0;
            const float gg0 = sideA ? d2 : p2, go0 = sideA ? p2 : d2;
            const float gi1 = sideA ? d1 : p1, gf1 = sideA ? p1 : d1;
            const float gg1 = sideA ? d3 : p3, go1 = sideA ? p3 : d3;

            const float iv0 = sigm(gi0), fv0 = sigm(gf0), gv0 = htanh(gg0), ov0 = sigm(go0);
            const float iv1 = sigm(gi1), fv1 = sigm(gf1), gv1 = htanh(gg1), ov1 = sigm(go1);
            cst0 = fv0 * cst0 + iv0 * gv0;
            cst1 = fv1 * cst1 + iv1 * gv1;
            const float h0 = ov0 * htanh(cst0);
            const float h1 = ov1 * htanh(cst1);

            if (sideA) {   // h(t) -> B-tile h slot t&1 (bf16 hi/lo)
                const int hw = 128 + 64 * (t & 1) + cell;
                float hh0 = bfr(h0), hh1 = bfr(h1);
                in_hi[r0][hw] = __float2bfloat16(hh0);
                in_lo[r0][hw] = __float2bfloat16(h0 - hh0);
                in_hi[r1][hw] = __float2bfloat16(hh1);
                in_lo[r1][hw] = __float2bfloat16(h1 - hh1);
            } else {       // f32 h(t) -> parity staging
                h_out[t & 1][r0][cell] = h0;
                h_out[t & 1][r1][cell] = h1;
            }
        } else {
            // ---- producer: flush h(t-1), gx(t+1), stage x(t+2), LDG x(t+3) ----
            if (t > 0 && sr < nrows) {
                if constexpr (!LAST)
                    outs[((size_t)(t - 1) * BnP + b0 + sr) * 64 + sc] =
                        h_out[(t - 1) & 1][sr][sc];
            }
            if (t + 1 < Tn)
                gx[(t + 1) & 1][cw][lane] = xproj((t + 1) & 1);
            if (t + 2 < Tn) {   // stage x(t+2) from reg into x slot t&1
                float hh = bfr(xreg);
                const int xb = 64 * (t & 1);
                in_hi[sr][xb + sc] = __float2bfloat16(hh);
                in_lo[sr][xb + sc] = __float2bfloat16(xreg - hh);
            }
            xreg = (t + 3 < Tn) ? xin[((size_t)(t + 3) * BnP + b0 + sr) * 64 + sc] : 0.f;
        }
    }

    __syncthreads();
    if constexpr (!LAST) {
        if (prod && sr < nrows)
            outs[((size_t)(Tn - 1) * BnP + b0 + sr) * 64 + sc] =
                h_out[(Tn - 1) & 1][sr][sc];
    } else {
        if (tid < nrows * 4) {
            const int r = tid >> 2, o = tid & 3;
            float s = b_fc[o];
#pragma unroll
            for (int k = 0; k < Hn; k++)
                s += h_out[(Tn - 1) & 1][r][k] * w_fc[o * Hn + k];
            out_fc[(b0 + r) * 4 + o] = s;
        }
    }
}

extern "C" void kernel_launch(void* const* d_in, const int* in_sizes, int n_in,
                              void* d_out, int out_size)
{
    const float* x    = (const float*)d_in[0];
    const float* wih0 = (const float*)d_in[1];
    const float* whh0 = (const float*)d_in[2];
    const float* bih0 = (const float*)d_in[3];
    const float* bhh0 = (const float*)d_in[4];
    const float* wih1 = (const float*)d_in[5];
    const float* whh1 = (const float*)d_in[6];
    const float* bih1 = (const float*)d_in[7];
    const float* bhh1 = (const float*)d_in[8];
    const float* wih2 = (const float*)d_in[9];
    const float* whh2 = (const float*)d_in[10];
    const float* bih2 = (const float*)d_in[11];
    const float* bhh2 = (const float*)d_in[12];
    const float* wfc  = (const float*)d_in[13];
    const float* bfc  = (const float*)d_in[14];
    float* out = (float*)d_out;

    transpose_x_k<<<Bn * 8, 256>>>(x);

    dim3 grid(GRID);
    dim3 block(NT);
    lstm_hmma_k<0><<<grid, block>>>(wih0, whh0, bih0, bhh0, nullptr, nullptr, nullptr);
    lstm_hmma_k<1><<<grid, block>>>(wih1, whh1, bih1, bhh1, nullptr, nullptr, nullptr);
    lstm_hmma_k<2><<<grid, block>>>(wih2, whh2, bih2, bhh2, wfc,     bfc,     out);
}

// round 12
// speedup vs baseline: 1.4067x; 1.4067x over previous
#include <cuda_runtime.h>
#include <cuda_bf16.h>
#include <cstdint>
#include <cstddef>

namespace {
constexpr int Bn   = 1024;
constexpr int BnP  = 1032;   // padded rows (zero tail)
constexpr int Tn   = 512;
constexpr int Hn   = 64;
constexpr int NB   = 7;      // real rows per block -> grid 147 (N=8 with pad row)
constexpr int GRID = 147;
constexpr int NT   = 512;    // 16 warps
}

// Inter-layer activations, [t][b][64], f32, rows >=1024 stay zero.
__device__ float g_seq0[(size_t)Tn * BnP * 64];
__device__ float g_seq1[(size_t)Tn * BnP * 64];
// Layer-0 input transposed+padded: [t][b][64] (cols 22..63 zero)
__device__ float g_x64[(size_t)Tn * BnP * 64];

__device__ __forceinline__ float htanh(float x) {   // HW MUFU.TANH
    float y;
    asm("tanh.approx.f32 %0, %1;" : "=f"(y) : "f"(x));
    return y;
}
__device__ __forceinline__ float sigm(float x) {    // 0.5 + 0.5*tanh(x/2)
    return fmaf(htanh(0.5f * x), 0.5f, 0.5f);
}
__device__ __forceinline__ uint32_t bf2(float a, float b) {
    __nv_bfloat162 t = __floats2bfloat162_rn(a, b);
    return *reinterpret_cast<uint32_t*>(&t);
}
__device__ __forceinline__ float bfr(float v) {
    return __bfloat162float(__float2bfloat16(v));
}

// m16n8k16 bf16 MMA, fp32 accumulate (sm_80 baseline PTX).
__device__ __forceinline__ void hmma(float& d0, float& d1, float& d2, float& d3,
                                     uint32_t a0, uint32_t a1, uint32_t a2, uint32_t a3,
                                     uint32_t b0, uint32_t b1) {
    asm volatile(
        "mma.sync.aligned.m16n8k16.row.col.f32.bf16.bf16.f32 "
        "{%0,%1,%2,%3}, {%4,%5,%6,%7}, {%8,%9}, {%0,%1,%2,%3};"
        : "+f"(d0), "+f"(d1), "+f"(d2), "+f"(d3)
        : "r"(a0), "r"(a1), "r"(a2), "r"(a3), "r"(b0), "r"(b1));
}

// Transpose x[b][22][t] -> g_x64[t][b][0..63] (cols 22..63 zero).
__global__ void __launch_bounds__(256)
transpose_x_k(const float* __restrict__ x)
{
    const int b  = blockIdx.x >> 3;
    const int t0 = (blockIdx.x & 7) * 64;
    __shared__ float tile[22][65];
    for (int e = threadIdx.x; e < 22 * 64; e += 256) {
        int i = e / 64, tt = e - i * 64;
        tile[i][tt] = x[(size_t)b * (22 * Tn) + i * Tn + t0 + tt];
    }
    __syncthreads();
    for (int e = threadIdx.x; e < 64 * 64; e += 256) {
        int tt = e >> 6, i = e & 63;
        g_x64[((size_t)(t0 + tt) * BnP + b) * 64 + i] = (i < 22) ? tile[i][tt] : 0.f;
    }
}

// LSTM layer, HMMA tensor cores, warp-local row-split combine.
// B operands live in a uint4 fragment tile bq[8 rows][68]:
//   per (row, slot, kc, qid): uint4(bh0, bh1, bl0, bl1)  — exactly one lane's
//   B-fragment per k-chunk -> ONE LDS.128 per kc per projection.
// Slots (uint4 offset within row): x0=0, x1=16, h0=32, h1=48 (all parity-buffered).
// Row stride 68 uint4 (mod 8 = 4) -> conflict-free LDS.128 phases.
// Warp w's m16 A-tile rows (gathered weight loads):
//   gid 0..7:  gate (gid>>2 ? f : i), cell 4w + (gid&3)
//   gid+8:     gate (gid>>2 ? o : g), cell 4w + (gid&3)
// After MMA + 2 side-selected shfls, sideA (lane<16) combines row 2qid,
// sideB row 2qid+1 — no duplicated MUFU work. ONE __syncthreads per step.
template<int LAYER>
__global__ void __launch_bounds__(NT, 1)
lstm_hmma_k(const float* __restrict__ w_ih, const float* __restrict__ w_hh,
            const float* __restrict__ b_ih, const float* __restrict__ b_hh,
            const float* __restrict__ w_fc, const float* __restrict__ b_fc,
            float* __restrict__ out_fc)
{
    constexpr bool LAST = (LAYER == 2);
    constexpr int  DIN  = (LAYER == 0) ? 22 : 64;
    constexpr int  XCH  = (LAYER == 0) ? 2 : 4;     // x k-chunks (cols >=32 zero for L0)
    const float* xin  = (LAYER == 0) ? g_x64 : (LAYER == 1 ? g_seq0 : g_seq1);
    float*       outs = (LAYER == 0) ? g_seq0 : (LAYER == 1 ? g_seq1 : nullptr);

    __shared__ __align__(16) uint4 bq[8][68];   // fragment tile
    __shared__ float h_out[2][8][68];           // parity f32 h staging

    const int tid  = threadIdx.x;
    const int lane = tid & 31;
    const int wrp  = tid >> 5;
    const int gid  = lane >> 2;          // 0..7
    const int qid  = lane & 3;           // 0..3
    const int b0   = blockIdx.x * NB;
    const int nrows = (Bn - b0 < NB) ? (Bn - b0) : NB;

    // permuted weight rows
    const int cell = 4 * wrp + (gid & 3);
    const int m0 = ((gid >> 2) ? 64 : 0)    + cell;   // i or f row
    const int m1 = ((gid >> 2) ? 192 : 128) + cell;   // g or o row

    // ---- weight fragments (hi + lo bf16 split), registers ----
    uint32_t axh[XCH][4], axl[XCH][4];   // W_x
    uint32_t ahh[4][4],   ahl[4][4];     // W_h
    {
        auto pair = [&](float p0, float p1, uint32_t& hi, uint32_t& lo) {
            float h0 = bfr(p0), h1 = bfr(p1);
            hi = bf2(h0, h1);
            lo = bf2(p0 - h0, p1 - h1);
        };
        auto wx = [&](int m, int k) -> float {
            return (k < DIN) ? w_ih[m * DIN + k] : 0.f;
        };
#pragma unroll
        for (int kc = 0; kc < XCH; kc++) {
            const int k0 = kc * 16 + qid * 2, k1 = k0 + 8;
            pair(wx(m0, k0), wx(m0, k0 + 1), axh[kc][0], axl[kc][0]);
            pair(wx(m1, k0), wx(m1, k0 + 1), axh[kc][1], axl[kc][1]);
            pair(wx(m0, k1), wx(m0, k1 + 1), axh[kc][2], axl[kc][2]);
            pair(wx(m1, k1), wx(m1, k1 + 1), axh[kc][3], axl[kc][3]);
        }
#pragma unroll
        for (int kc = 0; kc < 4; kc++) {
            const int k0 = kc * 16 + qid * 2, k1 = k0 + 8;
            pair(w_hh[m0 * 64 + k0], w_hh[m0 * 64 + k0 + 1], ahh[kc][0], ahl[kc][0]);
            pair(w_hh[m1 * 64 + k0], w_hh[m1 * 64 + k0 + 1], ahh[kc][1], ahl[kc][1]);
            pair(w_hh[m0 * 64 + k1], w_hh[m0 * 64 + k1 + 1], ahh[kc][2], ahl[kc][2]);
            pair(w_hh[m1 * 64 + k1], w_hh[m1 * 64 + k1 + 1], ahh[kc][3], ahl[kc][3]);
        }
    }
    const float biasA = b_ih[m0] + b_hh[m0];
    const float biasB = b_ih[m1] + b_hh[m1];

    // combine identities (row-split)
    const bool sideA = (lane < 16);
    const int  myrow = 2 * qid + (sideA ? 0 : 1);
    float cst = 0.f;

    // staging identity (coalesced)
    const int sr = tid >> 6, sc = tid & 63;
    // x-staging write decomposition for k-index sc: kc, qid, half, byte
    const int w_kc  = sc >> 4;
    const int w_qid = (sc >> 1) & 3;
    const int w_half = (sc >> 3) & 1;
    const int w_b   = sc & 1;

    // helper: write value v (hi/lo bf16) for (row, k=sc-like idx) into slot S
    auto put = [&](int row, int S, int kc, int qq, int half, int bb, float v) {
        __nv_bfloat16* p = reinterpret_cast<__nv_bfloat16*>(&bq[row][S + kc * 4 + qq]);
        float hv = bfr(v);
        p[half * 2 + bb]     = __float2bfloat16(hv);
        p[4 + half * 2 + bb] = __float2bfloat16(v - hv);
    };

    // ---- zero fragment tile ----
    for (int e = tid; e < 8 * 68 * 4; e += NT)
        reinterpret_cast<uint32_t*>(&bq[0][0])[e] = 0u;
    __syncthreads();
    // stage x(0) -> slot x0, x(1) -> slot x1
    {
        float v0 = xin[((size_t)0 * BnP + b0 + sr) * 64 + sc];
        put(sr, 0, w_kc, w_qid, w_half, w_b, v0);
        float v1 = (Tn > 1) ? xin[((size_t)1 * BnP + b0 + sr) * 64 + sc] : 0.f;
        put(sr, 16, w_kc, w_qid, w_half, w_b, v1);
    }
    __syncthreads();

    const uint4* myrowq = &bq[gid][qid];

    // xproj(slot parity): W_x · x + bias -> carried cx (3-term bf16 split)
    float cx0, cx1, cx2, cx3;
    auto xproj = [&](int slot) {
        float d0 = biasA, d1 = biasA, d2 = biasB, d3 = biasB;
        float e0 = 0.f, e1 = 0.f, e2 = 0.f, e3 = 0.f;
        float f0 = 0.f, f1 = 0.f, f2 = 0.f, f3 = 0.f;
        const int S = 16 * slot;
#pragma unroll
        for (int kc = 0; kc < XCH; kc++) {
            const uint4 v = myrowq[S + kc * 4];
            hmma(d0, d1, d2, d3, axh[kc][0], axh[kc][1], axh[kc][2], axh[kc][3], v.x, v.y);
            hmma(e0, e1, e2, e3, axh[kc][0], axh[kc][1], axh[kc][2], axh[kc][3], v.z, v.w);
            hmma(f0, f1, f2, f3, axl[kc][0], axl[kc][1], axl[kc][2], axl[kc][3], v.x, v.y);
        }
        cx0 = d0 + e0 + f0; cx1 = d1 + e1 + f1;
        cx2 = d2 + e2 + f2; cx3 = d3 + e3 + f3;
    };

    xproj(0);   // carried for t=0

    for (int t = 0; t < Tn; t++) {
        __syncthreads();   // ONE barrier: h(t-1), x slots, h_out(t-1) all ready

        // ---- coalesced flush of h(t-1) to global (off critical path) ----
        if (t > 0 && sr < nrows) {
            if constexpr (!LAST)
                outs[((size_t)(t - 1) * BnP + b0 + sr) * 64 + sc] =
                    h_out[(t - 1) & 1][sr][sc];
        }

        // ---- critical path: W_h · h(t-1) from h slot (t+1)&1, init = cx ----
        float d0 = cx0, d1 = cx1, d2 = cx2, d3 = cx3;
        float e0 = 0.f, e1 = 0.f, e2 = 0.f, e3 = 0.f;
        float f0 = 0.f, f1 = 0.f, f2 = 0.f, f3 = 0.f;
        const int hS = 32 + 16 * ((t + 1) & 1);
#pragma unroll
        for (int kc = 0; kc < 4; kc++) {
            const uint4 v = myrowq[hS + kc * 4];
            hmma(d0, d1, d2, d3, ahh[kc][0], ahh[kc][1], ahh[kc][2], ahh[kc][3], v.x, v.y);
            hmma(e0, e1, e2, e3, ahh[kc][0], ahh[kc][1], ahh[kc][2], ahh[kc][3], v.z, v.w);
            hmma(f0, f1, f2, f3, ahl[kc][0], ahl[kc][1], ahl[kc][2], ahl[kc][3], v.x, v.y);
        }
        d0 += e0 + f0; d1 += e1 + f1; d2 += e2 + f2; d3 += e3 + f3;

        // ---- off-path: xproj(t+1) (independent accumulators fill tensor pipe)
        if (t + 1 < Tn) xproj((t + 1) & 1);

        // prefetch x(t+2)
        float xn = 0.f;
        if (t + 2 < Tn)
            xn = xin[((size_t)(t + 2) * BnP + b0 + sr) * 64 + sc];

        // ---- row-split gate gather: 2 side-selected shfls ----
        // sideA (row r0) needs f0,o0 = partner's d0,d2; sideB (row r1) needs i1,g1.
        const float s1 = __shfl_xor_sync(0xffffffffu, sideA ? d1 : d0, 16);
        const float s2 = __shfl_xor_sync(0xffffffffu, sideA ? d3 : d2, 16);
        const float gi = sideA ? d0 : s1;
        const float gf = sideA ? s1 : d1;
        const float gg = sideA ? d2 : s2;
        const float go = sideA ? s2 : d3;

        // ---- combine: one (cell, row) per lane ----
        const float iv = sigm(gi), fv = sigm(gf), gv = htanh(gg), ov = sigm(go);
        cst = fv * cst + iv * gv;
        const float h = ov * htanh(cst);

        // h(t) -> h slot t&1 of fragment tile + f32 staging
        {
            const int hw = 32 + 16 * (t & 1);
            put(myrow, hw, cell >> 4, (cell >> 1) & 3, (cell >> 3) & 1, cell & 1, h);
            h_out[t & 1][myrow][cell] = h;
        }
        // x(t+2) -> x slot t&1
        if (t + 2 < Tn)
            put(sr, 16 * (t & 1), w_kc, w_qid, w_half, w_b, xn);
    }

    __syncthreads();
    if constexpr (!LAST) {
        if (sr < nrows)
            outs[((size_t)(Tn - 1) * BnP + b0 + sr) * 64 + sc] =
                h_out[(Tn - 1) & 1][sr][sc];
    } else {
        if (tid < nrows * 4) {
            const int r = tid >> 2, o = tid & 3;
            float s = b_fc[o];
#pragma unroll
            for (int k = 0; k < Hn; k++)
                s += h_out[(Tn - 1) & 1][r][k] * w_fc[o * Hn + k];
            out_fc[(b0 + r) * 4 + o] = s;
        }
    }
}

extern "C" void kernel_launch(void* const* d_in, const int* in_sizes, int n_in,
                              void* d_out, int out_size)
{
    const float* x    = (const float*)d_in[0];
    const float* wih0 = (const float*)d_in[1];
    const float* whh0 = (const float*)d_in[2];
    const float* bih0 = (const float*)d_in[3];
    const float* bhh0 = (const float*)d_in[4];
    const float* wih1 = (const float*)d_in[5];
    const float* whh1 = (const float*)d_in[6];
    const float* bih1 = (const float*)d_in[7];
    const float* bhh1 = (const float*)d_in[8];
    const float* wih2 = (const float*)d_in[9];
    const float* whh2 = (const float*)d_in[10];
    const float* bih2 = (const float*)d_in[11];
    const float* bhh2 = (const float*)d_in[12];
    const float* wfc  = (const float*)d_in[13];
    const float* bfc  = (const float*)d_in[14];
    float* out = (float*)d_out;

    transpose_x_k<<<Bn * 8, 256>>>(x);

    dim3 grid(GRID);
    dim3 block(NT);
    lstm_hmma_k<0><<<grid, block>>>(wih0, whh0, bih0, bhh0, nullptr, nullptr, nullptr);
    lstm_hmma_k<1><<<grid, block>>>(wih1, whh1, bih1, bhh1, nullptr, nullptr, nullptr);
    lstm_hmma_k<2><<<grid, block>>>(wih2, whh2, bih2, bhh2, wfc,     bfc,     out);
}

// round 13
// speedup vs baseline: 1.4720x; 1.0464x over previous
#include <cuda_runtime.h>
#include <cuda_fp16.h>
#include <cstdint>
#include <cstddef>

namespace {
constexpr int Bn   = 1024;
constexpr int BnP  = 1032;   // padded rows (zero tail)
constexpr int Tn   = 512;
constexpr int Hn   = 64;
constexpr int NB   = 7;      // real rows per block -> grid 147 (N=8 with pad row)
constexpr int GRID = 147;
constexpr int NT   = 512;    // 16 warps
}

// Inter-layer activations, [t][b][64], f32, rows >=1024 stay zero.
__device__ float g_seq0[(size_t)Tn * BnP * 64];
__device__ float g_seq1[(size_t)Tn * BnP * 64];
// Layer-0 input transposed+padded: [t][b][64] (cols 22..63 zero)
__device__ float g_x64[(size_t)Tn * BnP * 64];

__device__ __forceinline__ float htanh(float x) {   // HW MUFU.TANH
    float y;
    asm("tanh.approx.f32 %0, %1;" : "=f"(y) : "f"(x));
    return y;
}
__device__ __forceinline__ float sigm(float x) {    // 0.5 + 0.5*tanh(x/2)
    return fmaf(htanh(0.5f * x), 0.5f, 0.5f);
}
__device__ __forceinline__ uint32_t h2pk(float a, float b) {   // fp16x2 pack
    __half2 t = __floats2half2_rn(a, b);
    return *reinterpret_cast<uint32_t*>(&t);
}
__device__ __forceinline__ float hfr(float v) {     // round to fp16, back to f32
    return __half2float(__float2half_rn(v));
}

// m16n8k16 fp16 MMA, fp32 accumulate (sm_80 baseline PTX).
__device__ __forceinline__ void hmma(float& d0, float& d1, float& d2, float& d3,
                                     uint32_t a0, uint32_t a1, uint32_t a2, uint32_t a3,
                                     uint32_t b0, uint32_t b1) {
    asm volatile(
        "mma.sync.aligned.m16n8k16.row.col.f32.f16.f16.f32 "
        "{%0,%1,%2,%3}, {%4,%5,%6,%7}, {%8,%9}, {%0,%1,%2,%3};"
        : "+f"(d0), "+f"(d1), "+f"(d2), "+f"(d3)
        : "r"(a0), "r"(a1), "r"(a2), "r"(a3), "r"(b0), "r"(b1));
}

// Transpose x[b][22][t] -> g_x64[t][b][0..63] (cols 22..63 zero).
__global__ void __launch_bounds__(256)
transpose_x_k(const float* __restrict__ x)
{
    const int b  = blockIdx.x >> 3;
    const int t0 = (blockIdx.x & 7) * 64;
    __shared__ float tile[22][65];
    for (int e = threadIdx.x; e < 22 * 64; e += 256) {
        int i = e / 64, tt = e - i * 64;
        tile[i][tt] = x[(size_t)b * (22 * Tn) + i * Tn + t0 + tt];
    }
    __syncthreads();
    for (int e = threadIdx.x; e < 64 * 64; e += 256) {
        int tt = e >> 6, i = e & 63;
        g_x64[((size_t)(t0 + tt) * BnP + b) * 64 + i] = (i < 22) ? tile[i][tt] : 0.f;
    }
}

// LSTM layer, HMMA fp16 tensor cores, 2-term split (Whi*Bhi + Whi*Blo),
// warp-local row-split combine. B operands in uint4 fragment tile bq[8][68]:
//   per (row, slot, kc, qid): uint4(bh0, bh1, bl0, bl1) -> ONE LDS.128/kc/proj.
// Slots: x0=0, x1=16, h0=32, h1=48 (uint4 offsets, parity-buffered).
// Warp w's m16 A-tile rows (gathered, permuted):
//   gid 0..7: gate (gid>>2 ? f : i), cell 4w+(gid&3); gid+8: (o : g) same cell.
// After MMA + 2 side-selected shfls, sideA (lane<16) combines row 2qid,
// sideB row 2qid+1. ONE __syncthreads per step.
template<int LAYER>
__global__ void __launch_bounds__(NT, 1)
lstm_hmma_k(const float* __restrict__ w_ih, const float* __restrict__ w_hh,
            const float* __restrict__ b_ih, const float* __restrict__ b_hh,
            const float* __restrict__ w_fc, const float* __restrict__ b_fc,
            float* __restrict__ out_fc)
{
    constexpr bool LAST = (LAYER == 2);
    constexpr int  DIN  = (LAYER == 0) ? 22 : 64;
    constexpr int  XCH  = (LAYER == 0) ? 2 : 4;     // x k-chunks (cols >=32 zero for L0)
    const float* xin  = (LAYER == 0) ? g_x64 : (LAYER == 1 ? g_seq0 : g_seq1);
    float*       outs = (LAYER == 0) ? g_seq0 : (LAYER == 1 ? g_seq1 : nullptr);

    __shared__ __align__(16) uint4 bq[8][68];   // fragment tile
    __shared__ float h_out[2][8][68];           // parity f32 h staging

    const int tid  = threadIdx.x;
    const int lane = tid & 31;
    const int wrp  = tid >> 5;
    const int gid  = lane >> 2;          // 0..7
    const int qid  = lane & 3;           // 0..3
    const int b0   = blockIdx.x * NB;
    const int nrows = (Bn - b0 < NB) ? (Bn - b0) : NB;

    // permuted weight rows
    const int cell = 4 * wrp + (gid & 3);
    const int m0 = ((gid >> 2) ? 64 : 0)    + cell;   // i or f row
    const int m1 = ((gid >> 2) ? 192 : 128) + cell;   // g or o row

    // ---- weight fragments: fp16(W) only (2-term split), registers ----
    uint32_t axh[XCH][4];   // W_x
    uint32_t ahh[4][4];     // W_h
    {
        auto wx = [&](int m, int k) -> float {
            return (k < DIN) ? w_ih[m * DIN + k] : 0.f;
        };
#pragma unroll
        for (int kc = 0; kc < XCH; kc++) {
            const int k0 = kc * 16 + qid * 2, k1 = k0 + 8;
            axh[kc][0] = h2pk(wx(m0, k0), wx(m0, k0 + 1));
            axh[kc][1] = h2pk(wx(m1, k0), wx(m1, k0 + 1));
            axh[kc][2] = h2pk(wx(m0, k1), wx(m0, k1 + 1));
            axh[kc][3] = h2pk(wx(m1, k1), wx(m1, k1 + 1));
        }
#pragma unroll
        for (int kc = 0; kc < 4; kc++) {
            const int k0 = kc * 16 + qid * 2, k1 = k0 + 8;
            ahh[kc][0] = h2pk(w_hh[m0 * 64 + k0], w_hh[m0 * 64 + k0 + 1]);
            ahh[kc][1] = h2pk(w_hh[m1 * 64 + k0], w_hh[m1 * 64 + k0 + 1]);
            ahh[kc][2] = h2pk(w_hh[m0 * 64 + k1], w_hh[m0 * 64 + k1 + 1]);
            ahh[kc][3] = h2pk(w_hh[m1 * 64 + k1], w_hh[m1 * 64 + k1 + 1]);
        }
    }
    const float biasA = b_ih[m0] + b_hh[m0];
    const float biasB = b_ih[m1] + b_hh[m1];

    // combine identities (row-split)
    const bool sideA = (lane < 16);
    const int  myrow = 2 * qid + (sideA ? 0 : 1);
    float cst = 0.f;

    // staging identity (coalesced)
    const int sr = tid >> 6, sc = tid & 63;
    const int w_kc  = sc >> 4;
    const int w_qid = (sc >> 1) & 3;
    const int w_half = (sc >> 3) & 1;
    const int w_b   = sc & 1;

    // write value v (hi/lo fp16) for (row, k) into slot S
    auto put = [&](int row, int S, int kc, int qq, int half, int bb, float v) {
        __half* p = reinterpret_cast<__half*>(&bq[row][S + kc * 4 + qq]);
        float hv = hfr(v);
        p[half * 2 + bb]     = __float2half_rn(hv);
        p[4 + half * 2 + bb] = __float2half_rn(v - hv);
    };

    // ---- zero fragment tile ----
    for (int e = tid; e < 8 * 68 * 4; e += NT)
        reinterpret_cast<uint32_t*>(&bq[0][0])[e] = 0u;
    __syncthreads();
    // stage x(0) -> slot x0, x(1) -> slot x1
    {
        float v0 = xin[((size_t)0 * BnP + b0 + sr) * 64 + sc];
        put(sr, 0, w_kc, w_qid, w_half, w_b, v0);
        float v1 = (Tn > 1) ? xin[((size_t)1 * BnP + b0 + sr) * 64 + sc] : 0.f;
        put(sr, 16, w_kc, w_qid, w_half, w_b, v1);
    }
    __syncthreads();

    const uint4* myrowq = &bq[gid][qid];

    // xproj(slot parity): W_x · x + bias -> carried cx (2-term split)
    float cx0, cx1, cx2, cx3;
    auto xproj = [&](int slot) {
        float d0 = biasA, d1 = biasA, d2 = biasB, d3 = biasB;
        float e0 = 0.f, e1 = 0.f, e2 = 0.f, e3 = 0.f;
        const int S = 16 * slot;
#pragma unroll
        for (int kc = 0; kc < XCH; kc++) {
            const uint4 v = myrowq[S + kc * 4];
            hmma(d0, d1, d2, d3, axh[kc][0], axh[kc][1], axh[kc][2], axh[kc][3], v.x, v.y);
            hmma(e0, e1, e2, e3, axh[kc][0], axh[kc][1], axh[kc][2], axh[kc][3], v.z, v.w);
        }
        cx0 = d0 + e0; cx1 = d1 + e1; cx2 = d2 + e2; cx3 = d3 + e3;
    };

    xproj(0);   // carried for t=0

    for (int t = 0; t < Tn; t++) {
        __syncthreads();   // ONE barrier: h(t-1), x slots, h_out(t-1) all ready

        // ---- coalesced flush of h(t-1) to global (off critical path) ----
        if (t > 0 && sr < nrows) {
            if constexpr (!LAST)
                outs[((size_t)(t - 1) * BnP + b0 + sr) * 64 + sc] =
                    h_out[(t - 1) & 1][sr][sc];
        }

        // ---- critical path: W_h · h(t-1), 4 depth-2 chains, init = cx ----
        float d0 = cx0, d1 = cx1, d2 = cx2, d3 = cx3;       // hi, kc 0-1
        float e0 = 0.f, e1 = 0.f, e2 = 0.f, e3 = 0.f;       // lo, kc 0-1
        float p0 = 0.f, p1 = 0.f, p2 = 0.f, p3 = 0.f;       // hi, kc 2-3
        float q0 = 0.f, q1 = 0.f, q2 = 0.f, q3 = 0.f;       // lo, kc 2-3
        const int hS = 32 + 16 * ((t + 1) & 1);
        {
            const uint4 v0 = myrowq[hS];
            const uint4 v1 = myrowq[hS + 4];
            const uint4 v2 = myrowq[hS + 8];
            const uint4 v3 = myrowq[hS + 12];
            hmma(d0, d1, d2, d3, ahh[0][0], ahh[0][1], ahh[0][2], ahh[0][3], v0.x, v0.y);
            hmma(p0, p1, p2, p3, ahh[2][0], ahh[2][1], ahh[2][2], ahh[2][3], v2.x, v2.y);
            hmma(e0, e1, e2, e3, ahh[0][0], ahh[0][1], ahh[0][2], ahh[0][3], v0.z, v0.w);
            hmma(q0, q1, q2, q3, ahh[2][0], ahh[2][1], ahh[2][2], ahh[2][3], v2.z, v2.w);
            hmma(d0, d1, d2, d3, ahh[1][0], ahh[1][1], ahh[1][2], ahh[1][3], v1.x, v1.y);
            hmma(p0, p1, p2, p3, ahh[3][0], ahh[3][1], ahh[3][2], ahh[3][3], v3.x, v3.y);
            hmma(e0, e1, e2, e3, ahh[1][0], ahh[1][1], ahh[1][2], ahh[1][3], v1.z, v1.w);
            hmma(q0, q1, q2, q3, ahh[3][0], ahh[3][1], ahh[3][2], ahh[3][3], v3.z, v3.w);
        }
        d0 += e0 + p0 + q0; d1 += e1 + p1 + q1;
        d2 += e2 + p2 + q2; d3 += e3 + p3 + q3;

        // ---- off-path: xproj(t+1) (independent accumulators fill tensor pipe)
        if (t + 1 < Tn) xproj((t + 1) & 1);

        // prefetch x(t+2)
        float xn = 0.f;
        if (t + 2 < Tn)
            xn = xin[((size_t)(t + 2) * BnP + b0 + sr) * 64 + sc];

        // ---- row-split gate gather: 2 side-selected shfls ----
        const float s1 = __shfl_xor_sync(0xffffffffu, sideA ? d1 : d0, 16);
        const float s2 = __shfl_xor_sync(0xffffffffu, sideA ? d3 : d2, 16);
        const float gi = sideA ? d0 : s1;
        const float gf = sideA ? s1 : d1;
        const float gg = sideA ? d2 : s2;
        const float go = sideA ? s2 : d3;

        // ---- combine: one (cell, row) per lane ----
        const float iv = sigm(gi), fv = sigm(gf), gv = htanh(gg), ov = sigm(go);
        cst = fv * cst + iv * gv;
        const float h = ov * htanh(cst);

        // h(t) -> h slot t&1 of fragment tile + f32 staging
        {
            const int hw = 32 + 16 * (t & 1);
            put(myrow, hw, cell >> 4, (cell >> 1) & 3, (cell >> 3) & 1, cell & 1, h);
            h_out[t & 1][myrow][cell] = h;
        }
        // x(t+2) -> x slot t&1
        if (t + 2 < Tn)
            put(sr, 16 * (t & 1), w_kc, w_qid, w_half, w_b, xn);
    }

    __syncthreads();
    if constexpr (!LAST) {
        if (sr < nrows)
            outs[((size_t)(Tn - 1) * BnP + b0 + sr) * 64 + sc] =
                h_out[(Tn - 1) & 1][sr][sc];
    } else {
        if (tid < nrows * 4) {
            const int r = tid >> 2, o = tid & 3;
            float s = b_fc[o];
#pragma unroll
            for (int k = 0; k < Hn; k++)
                s += h_out[(Tn - 1) & 1][r][k] * w_fc[o * Hn + k];
            out_fc[(b0 + r) * 4 + o] = s;
        }
    }
}

extern "C" void kernel_launch(void* const* d_in, const int* in_sizes, int n_in,
                              void* d_out, int out_size)
{
    const float* x    = (const float*)d_in[0];
    const float* wih0 = (const float*)d_in[1];
    const float* whh0 = (const float*)d_in[2];
    const float* bih0 = (const float*)d_in[3];
    const float* bhh0 = (const float*)d_in[4];
    const float* wih1 = (const float*)d_in[5];
    const float* whh1 = (const float*)d_in[6];
    const float* bih1 = (const float*)d_in[7];
    const float* bhh1 = (const float*)d_in[8];
    const float* wih2 = (const float*)d_in[9];
    const float* whh2 = (const float*)d_in[10];
    const float* bih2 = (const float*)d_in[11];
    const float* bhh2 = (const float*)d_in[12];
    const float* wfc  = (const float*)d_in[13];
    const float* bfc  = (const float*)d_in[14];
    float* out = (float*)d_out;

    transpose_x_k<<<Bn * 8, 256>>>(x);

    dim3 grid(GRID);
    dim3 block(NT);
    lstm_hmma_k<0><<<grid, block>>>(wih0, whh0, bih0, bhh0, nullptr, nullptr, nullptr);
    lstm_hmma_k<1><<<grid, block>>>(wih1, whh1, bih1, bhh1, nullptr, nullptr, nullptr);
    lstm_hmma_k<2><<<grid, block>>>(wih2, whh2, bih2, bhh2, wfc,     bfc,     out);
}

// round 14
// speedup vs baseline: 1.7558x; 1.1928x over previous
#include <cuda_runtime.h>
#include <cuda_fp16.h>
#include <cstdint>
#include <cstddef>

namespace {
constexpr int Bn   = 1024;
constexpr int BnP  = 1032;   // padded rows (zero tail)
constexpr int Tn   = 512;
constexpr int Hn   = 64;
constexpr int NB   = 7;      // real rows per block -> grid 147 (N=8 with pad row)
constexpr int GRID = 147;
constexpr int NT   = 512;    // 16 warps
constexpr int RQ   = 36;     // bq row stride in uint4 (mod 8 = 4 -> conflict-free)
}

// Inter-layer activations, [t][b][64], f32, rows >=1024 stay zero.
__device__ float g_seq0[(size_t)Tn * BnP * 64];
__device__ float g_seq1[(size_t)Tn * BnP * 64];
// Layer-0 input transposed+padded: [t][b][64] (cols 22..63 zero)
__device__ float g_x64[(size_t)Tn * BnP * 64];

__device__ __forceinline__ float htanh(float x) {   // HW MUFU.TANH
    float y;
    asm("tanh.approx.f32 %0, %1;" : "=f"(y) : "f"(x));
    return y;
}
__device__ __forceinline__ float sigm(float x) {    // 0.5 + 0.5*tanh(x/2)
    return fmaf(htanh(0.5f * x), 0.5f, 0.5f);
}
__device__ __forceinline__ uint32_t h2pk(float a, float b) {   // fp16x2 pack
    __half2 t = __floats2half2_rn(a, b);
    return *reinterpret_cast<uint32_t*>(&t);
}

// m16n8k16 fp16 MMA, fp32 accumulate (sm_80 baseline PTX).
__device__ __forceinline__ void hmma(float& d0, float& d1, float& d2, float& d3,
                                     uint32_t a0, uint32_t a1, uint32_t a2, uint32_t a3,
                                     uint32_t b0, uint32_t b1) {
    asm volatile(
        "mma.sync.aligned.m16n8k16.row.col.f32.f16.f16.f32 "
        "{%0,%1,%2,%3}, {%4,%5,%6,%7}, {%8,%9}, {%0,%1,%2,%3};"
        : "+f"(d0), "+f"(d1), "+f"(d2), "+f"(d3)
        : "r"(a0), "r"(a1), "r"(a2), "r"(a3), "r"(b0), "r"(b1));
}

// Transpose x[b][22][t] -> g_x64[t][b][0..63] (cols 22..63 zero).
__global__ void __launch_bounds__(256)
transpose_x_k(const float* __restrict__ x)
{
    const int b  = blockIdx.x >> 3;
    const int t0 = (blockIdx.x & 7) * 64;
    __shared__ float tile[22][65];
    for (int e = threadIdx.x; e < 22 * 64; e += 256) {
        int i = e / 64, tt = e - i * 64;
        tile[i][tt] = x[(size_t)b * (22 * Tn) + i * Tn + t0 + tt];
    }
    __syncthreads();
    for (int e = threadIdx.x; e < 64 * 64; e += 256) {
        int tt = e >> 6, i = e & 63;
        g_x64[((size_t)(t0 + tt) * BnP + b) * 64 + i] = (i < 22) ? tile[i][tt] : 0.f;
    }
}

// LSTM layer, pure-fp16 HMMA GEMM (no lo-split), warp-local row-split combine.
// B operands in uint4 fragment tile bq[8][RQ]; per row, slots of 8 uint4:
//   x0 @ 0, x1 @ 8, h0 @ 16, h1 @ 24 (parity-buffered).
// Within a slot, uint4 index pair*4 + qid holds lane (.,qid)'s fragments for
// k-chunks {2*pair, 2*pair+1}: (b0[kc0], b1[kc0], b0[kc1], b1[kc1]).
// hproj = 2 LDS.128 + 4 HMMA; xproj = 1-2 LDS.128 + 2-4 HMMA.
// Warp w's m16 A-tile rows (gathered, permuted):
//   gid 0..7: gate (gid>>2 ? f : i), cell 4w+(gid&3); gid+8: (o : g) same cell.
// After MMA + 2 side-selected shfls, sideA (lane<16) combines row 2qid,
// sideB row 2qid+1. ONE __syncthreads per step.
template<int LAYER>
__global__ void __launch_bounds__(NT, 1)
lstm_hmma_k(const float* __restrict__ w_ih, const float* __restrict__ w_hh,
            const float* __restrict__ b_ih, const float* __restrict__ b_hh,
            const float* __restrict__ w_fc, const float* __restrict__ b_fc,
            float* __restrict__ out_fc)
{
    constexpr bool LAST = (LAYER == 2);
    constexpr int  DIN  = (LAYER == 0) ? 22 : 64;
    constexpr int  XCH  = (LAYER == 0) ? 2 : 4;     // x k-chunks (cols >=32 zero for L0)
    const float* xin  = (LAYER == 0) ? g_x64 : (LAYER == 1 ? g_seq0 : g_seq1);
    float*       outs = (LAYER == 0) ? g_seq0 : (LAYER == 1 ? g_seq1 : nullptr);

    __shared__ __align__(16) uint4 bq[8][RQ];   // fp16 fragment tile
    __shared__ float h_out[2][8][68];           // parity f32 h staging

    const int tid  = threadIdx.x;
    const int lane = tid & 31;
    const int wrp  = tid >> 5;
    const int gid  = lane >> 2;          // 0..7
    const int qid  = lane & 3;           // 0..3
    const int b0   = blockIdx.x * NB;
    const int nrows = (Bn - b0 < NB) ? (Bn - b0) : NB;

    // permuted weight rows
    const int cell = 4 * wrp + (gid & 3);
    const int m0 = ((gid >> 2) ? 64 : 0)    + cell;   // i or f row
    const int m1 = ((gid >> 2) ? 192 : 128) + cell;   // g or o row

    // ---- fp16 weight fragments, registers ----
    uint32_t axh[XCH][4];   // W_x
    uint32_t ahh[4][4];     // W_h
    {
        auto wx = [&](int m, int k) -> float {
            return (k < DIN) ? w_ih[m * DIN + k] : 0.f;
        };
#pragma unroll
        for (int kc = 0; kc < XCH; kc++) {
            const int k0 = kc * 16 + qid * 2, k1 = k0 + 8;
            axh[kc][0] = h2pk(wx(m0, k0), wx(m0, k0 + 1));
            axh[kc][1] = h2pk(wx(m1, k0), wx(m1, k0 + 1));
            axh[kc][2] = h2pk(wx(m0, k1), wx(m0, k1 + 1));
            axh[kc][3] = h2pk(wx(m1, k1), wx(m1, k1 + 1));
        }
#pragma unroll
        for (int kc = 0; kc < 4; kc++) {
            const int k0 = kc * 16 + qid * 2, k1 = k0 + 8;
            ahh[kc][0] = h2pk(w_hh[m0 * 64 + k0], w_hh[m0 * 64 + k0 + 1]);
            ahh[kc][1] = h2pk(w_hh[m1 * 64 + k0], w_hh[m1 * 64 + k0 + 1]);
            ahh[kc][2] = h2pk(w_hh[m0 * 64 + k1], w_hh[m0 * 64 + k1 + 1]);
            ahh[kc][3] = h2pk(w_hh[m1 * 64 + k1], w_hh[m1 * 64 + k1 + 1]);
        }
    }
    const float biasA = b_ih[m0] + b_hh[m0];
    const float biasB = b_ih[m1] + b_hh[m1];

    // combine identities (row-split)
    const bool sideA = (lane < 16);
    const int  myrow = 2 * qid + (sideA ? 0 : 1);
    float cst = 0.f;

    // staging identity (coalesced); decompose k-index sc once
    const int sr = tid >> 6, sc = tid & 63;
    const int xw_u4   = (sc >> 5) * 4 + ((sc >> 1) & 3);              // uint4 idx in slot
    const int xw_comp = (((sc >> 4) & 1) * 2 + ((sc >> 3) & 1)) * 2 + (sc & 1);
    // combine h-write decomposition of `cell`
    const int hw_u4   = (cell >> 5) * 4 + ((cell >> 1) & 3);
    const int hw_comp = (((cell >> 4) & 1) * 2 + ((cell >> 3) & 1)) * 2 + (cell & 1);

    // write fp16 value for k-index (pre-decomposed) into slot S (uint4 base)
    auto putx = [&](int row, int S, float v) {
        reinterpret_cast<__half*>(&bq[row][S + xw_u4])[xw_comp] = __float2half_rn(v);
    };

    // ---- zero fragment tile ----
    for (int e = tid; e < 8 * RQ * 4; e += NT)
        reinterpret_cast<uint32_t*>(&bq[0][0])[e] = 0u;
    __syncthreads();
    // stage x(0) -> slot x0 (base 0), x(1) -> slot x1 (base 8)
    {
        float v0 = xin[((size_t)0 * BnP + b0 + sr) * 64 + sc];
        putx(sr, 0, v0);
        float v1 = (Tn > 1) ? xin[((size_t)1 * BnP + b0 + sr) * 64 + sc] : 0.f;
        putx(sr, 8, v1);
    }
    __syncthreads();

    const uint4* myrowq = &bq[gid][qid];

    // xproj(slot parity): W_x · x + bias -> carried cx
    float cx0, cx1, cx2, cx3;
    auto xproj = [&](int slot) {
        float d0 = biasA, d1 = biasA, d2 = biasB, d3 = biasB;
        const int S = 8 * slot;
        const uint4 va = myrowq[S];
        hmma(d0, d1, d2, d3, axh[0][0], axh[0][1], axh[0][2], axh[0][3], va.x, va.y);
        hmma(d0, d1, d2, d3, axh[1][0], axh[1][1], axh[1][2], axh[1][3], va.z, va.w);
        if constexpr (XCH == 4) {
            const uint4 vb = myrowq[S + 4];
            hmma(d0, d1, d2, d3, axh[2][0], axh[2][1], axh[2][2], axh[2][3], vb.x, vb.y);
            hmma(d0, d1, d2, d3, axh[3][0], axh[3][1], axh[3][2], axh[3][3], vb.z, vb.w);
        }
        cx0 = d0; cx1 = d1; cx2 = d2; cx3 = d3;
    };

    xproj(0);   // carried for t=0

    for (int t = 0; t < Tn; t++) {
        __syncthreads();   // ONE barrier: h(t-1), x slots, h_out(t-1) all ready

        // ---- coalesced flush of h(t-1) to global (off critical path) ----
        if (t > 0 && sr < nrows) {
            if constexpr (!LAST)
                outs[((size_t)(t - 1) * BnP + b0 + sr) * 64 + sc] =
                    h_out[(t - 1) & 1][sr][sc];
        }

        // ---- critical path: W_h · h(t-1), 2 depth-2 chains, init = cx ----
        float d0 = cx0, d1 = cx1, d2 = cx2, d3 = cx3;   // kc pair 0
        float p0 = 0.f, p1 = 0.f, p2 = 0.f, p3 = 0.f;   // kc pair 1
        const int hS = 16 + 8 * ((t + 1) & 1);
        {
            const uint4 va = myrowq[hS];
            const uint4 vb = myrowq[hS + 4];
            hmma(d0, d1, d2, d3, ahh[0][0], ahh[0][1], ahh[0][2], ahh[0][3], va.x, va.y);
            hmma(p0, p1, p2, p3, ahh[2][0], ahh[2][1], ahh[2][2], ahh[2][3], vb.x, vb.y);
            hmma(d0, d1, d2, d3, ahh[1][0], ahh[1][1], ahh[1][2], ahh[1][3], va.z, va.w);
            hmma(p0, p1, p2, p3, ahh[3][0], ahh[3][1], ahh[3][2], ahh[3][3], vb.z, vb.w);
        }
        d0 += p0; d1 += p1; d2 += p2; d3 += p3;

        // ---- off-path: xproj(t+1) (independent accumulators fill tensor pipe)
        if (t + 1 < Tn) xproj((t + 1) & 1);

        // prefetch x(t+2)
        float xn = 0.f;
        if (t + 2 < Tn)
            xn = xin[((size_t)(t + 2) * BnP + b0 + sr) * 64 + sc];

        // ---- row-split gate gather: 2 side-selected shfls ----
        const float s1 = __shfl_xor_sync(0xffffffffu, sideA ? d1 : d0, 16);
        const float s2 = __shfl_xor_sync(0xffffffffu, sideA ? d3 : d2, 16);
        const float gi = sideA ? d0 : s1;
        const float gf = sideA ? s1 : d1;
        const float gg = sideA ? d2 : s2;
        const float go = sideA ? s2 : d3;

        // ---- combine: one (cell, row) per lane ----
        const float iv = sigm(gi), fv = sigm(gf), gv = htanh(gg), ov = sigm(go);
        cst = fv * cst + iv * gv;
        const float h = ov * htanh(cst);

        // h(t) -> h slot t&1 (single fp16 store) + f32 staging
        {
            const int hw = 16 + 8 * (t & 1);
            reinterpret_cast<__half*>(&bq[myrow][hw + hw_u4])[hw_comp] = __float2half_rn(h);
            h_out[t & 1][myrow][cell] = h;
        }
        // x(t+2) -> x slot t&1
        if (t + 2 < Tn)
            putx(sr, 8 * (t & 1), xn);
    }

    __syncthreads();
    if constexpr (!LAST) {
        if (sr < nrows)
            outs[((size_t)(Tn - 1) * BnP + b0 + sr) * 64 + sc] =
                h_out[(Tn - 1) & 1][sr][sc];
    } else {
        if (tid < nrows * 4) {
            const int r = tid >> 2, o = tid & 3;
            float s = b_fc[o];
#pragma unroll
            for (int k = 0; k < Hn; k++)
                s += h_out[(Tn - 1) & 1][r][k] * w_fc[o * Hn + k];
            out_fc[(b0 + r) * 4 + o] = s;
        }
    }
}

extern "C" void kernel_launch(void* const* d_in, const int* in_sizes, int n_in,
                              void* d_out, int out_size)
{
    const float* x    = (const float*)d_in[0];
    const float* wih0 = (const float*)d_in[1];
    const float* whh0 = (const float*)d_in[2];
    const float* bih0 = (const float*)d_in[3];
    const float* bhh0 = (const float*)d_in[4];
    const float* wih1 = (const float*)d_in[5];
    const float* whh1 = (const float*)d_in[6];
    const float* bih1 = (const float*)d_in[7];
    const float* bhh1 = (const float*)d_in[8];
    const float* wih2 = (const float*)d_in[9];
    const float* whh2 = (const float*)d_in[10];
    const float* bih2 = (const float*)d_in[11];
    const float* bhh2 = (const float*)d_in[12];
    const float* wfc  = (const float*)d_in[13];
    const float* bfc  = (const float*)d_in[14];
    float* out = (float*)d_out;

    transpose_x_k<<<Bn * 8, 256>>>(x);

    dim3 grid(GRID);
    dim3 block(NT);
    lstm_hmma_k<0><<<grid, block>>>(wih0, whh0, bih0, bhh0, nullptr, nullptr, nullptr);
    lstm_hmma_k<1><<<grid, block>>>(wih1, whh1, bih1, bhh1, nullptr, nullptr, nullptr);
    lstm_hmma_k<2><<<grid, block>>>(wih2, whh2, bih2, bhh2, wfc,     bfc,     out);
}

// round 15
// speedup vs baseline: 2.6289x; 1.4973x over previous
#include <cuda_runtime.h>
#include <cuda_fp16.h>
#include <cstdint>
#include <cstddef>

namespace {
constexpr int Bn   = 1024;
constexpr int BnP  = 1032;   // padded rows (zero tail)
constexpr int Tn   = 512;
constexpr int Hn   = 64;
constexpr int NB   = 7;      // real rows per block -> grid 147 (N=8 with pad row)
constexpr int GRID = 147;
constexpr int NT   = 512;    // 16 warps
constexpr int RQ   = 36;     // bq row stride in uint4 (mod 8 = 4 -> conflict-free)
}

// Inter-layer activations, [t][b][64], f32, rows >=1024 stay zero.
__device__ float g_seq0[(size_t)Tn * BnP * 64];
__device__ float g_seq1[(size_t)Tn * BnP * 64];
// Layer-0 input transposed+padded: [t][b][64] (cols 22..63 zero)
__device__ float g_x64[(size_t)Tn * BnP * 64];

__device__ __forceinline__ float htanh(float x) {   // HW MUFU.TANH
    float y;
    asm("tanh.approx.f32 %0, %1;" : "=f"(y) : "f"(x));
    return y;
}
__device__ __forceinline__ float sigm(float x) {    // 0.5 + 0.5*tanh(x/2)
    return fmaf(htanh(0.5f * x), 0.5f, 0.5f);
}
__device__ __forceinline__ uint32_t h2pk(float a, float b) {   // fp16x2 pack
    __half2 t = __floats2half2_rn(a, b);
    return *reinterpret_cast<uint32_t*>(&t);
}

// m16n8k16 fp16 MMA, fp32 accumulate (sm_80 baseline PTX).
__device__ __forceinline__ void hmma(float& d0, float& d1, float& d2, float& d3,
                                     uint32_t a0, uint32_t a1, uint32_t a2, uint32_t a3,
                                     uint32_t b0, uint32_t b1) {
    asm volatile(
        "mma.sync.aligned.m16n8k16.row.col.f32.f16.f16.f32 "
        "{%0,%1,%2,%3}, {%4,%5,%6,%7}, {%8,%9}, {%0,%1,%2,%3};"
        : "+f"(d0), "+f"(d1), "+f"(d2), "+f"(d3)
        : "r"(a0), "r"(a1), "r"(a2), "r"(a3), "r"(b0), "r"(b1));
}

// Transpose x[b][22][t] -> g_x64[t][b][0..63] (cols 22..63 zero).
__global__ void __launch_bounds__(256)
transpose_x_k(const float* __restrict__ x)
{
    const int b  = blockIdx.x >> 3;
    const int t0 = (blockIdx.x & 7) * 64;
    __shared__ float tile[22][65];
    for (int e = threadIdx.x; e < 22 * 64; e += 256) {
        int i = e / 64, tt = e - i * 64;
        tile[i][tt] = x[(size_t)b * (22 * Tn) + i * Tn + t0 + tt];
    }
    __syncthreads();
    for (int e = threadIdx.x; e < 64 * 64; e += 256) {
        int tt = e >> 6, i = e & 63;
        g_x64[((size_t)(t0 + tt) * BnP + b) * 64 + i] = (i < 22) ? tile[i][tt] : 0.f;
    }
}

// LSTM layer, pure-fp16 HMMA GEMM, warp-local row-split combine,
// 2-iteration-deep x prefetch pipeline (LDG->consume distance > DRAM latency).
// B operands in uint4 fragment tile bq[8][RQ]; per row, slots of 8 uint4:
//   x0 @ 0, x1 @ 8, h0 @ 16, h1 @ 24 (parity-buffered).
// Within a slot, uint4 index pair*4 + qid holds lane (.,qid)'s fragments for
// k-chunks {2*pair, 2*pair+1}: (b0[kc0], b1[kc0], b0[kc1], b1[kc1]).
// Warp w's m16 A-tile rows (gathered, permuted):
//   gid 0..7: gate (gid>>2 ? f : i), cell 4w+(gid&3); gid+8: (o : g) same cell.
// After MMA + 2 side-selected shfls, sideA (lane<16) combines row 2qid,
// sideB row 2qid+1. ONE __syncthreads per step.
template<int LAYER>
__global__ void __launch_bounds__(NT, 1)
lstm_hmma_k(const float* __restrict__ w_ih, const float* __restrict__ w_hh,
            const float* __restrict__ b_ih, const float* __restrict__ b_hh,
            const float* __restrict__ w_fc, const float* __restrict__ b_fc,
            float* __restrict__ out_fc)
{
    constexpr bool LAST = (LAYER == 2);
    constexpr int  DIN  = (LAYER == 0) ? 22 : 64;
    constexpr int  XCH  = (LAYER == 0) ? 2 : 4;     // x k-chunks (cols >=32 zero for L0)
    const float* xin  = (LAYER == 0) ? g_x64 : (LAYER == 1 ? g_seq0 : g_seq1);
    float*       outs = (LAYER == 0) ? g_seq0 : (LAYER == 1 ? g_seq1 : nullptr);

    __shared__ __align__(16) uint4 bq[8][RQ];   // fp16 fragment tile
    __shared__ float h_out[2][8][68];           // parity f32 h staging

    const int tid  = threadIdx.x;
    const int lane = tid & 31;
    const int wrp  = tid >> 5;
    const int gid  = lane >> 2;          // 0..7
    const int qid  = lane & 3;           // 0..3
    const int b0   = blockIdx.x * NB;
    const int nrows = (Bn - b0 < NB) ? (Bn - b0) : NB;

    // permuted weight rows
    const int cell = 4 * wrp + (gid & 3);
    const int m0 = ((gid >> 2) ? 64 : 0)    + cell;   // i or f row
    const int m1 = ((gid >> 2) ? 192 : 128) + cell;   // g or o row

    // ---- fp16 weight fragments, registers ----
    uint32_t axh[XCH][4];   // W_x
    uint32_t ahh[4][4];     // W_h
    {
        auto wx = [&](int m, int k) -> float {
            return (k < DIN) ? w_ih[m * DIN + k] : 0.f;
        };
#pragma unroll
        for (int kc = 0; kc < XCH; kc++) {
            const int k0 = kc * 16 + qid * 2, k1 = k0 + 8;
            axh[kc][0] = h2pk(wx(m0, k0), wx(m0, k0 + 1));
            axh[kc][1] = h2pk(wx(m1, k0), wx(m1, k0 + 1));
            axh[kc][2] = h2pk(wx(m0, k1), wx(m0, k1 + 1));
            axh[kc][3] = h2pk(wx(m1, k1), wx(m1, k1 + 1));
        }
#pragma unroll
        for (int kc = 0; kc < 4; kc++) {
            const int k0 = kc * 16 + qid * 2, k1 = k0 + 8;
            ahh[kc][0] = h2pk(w_hh[m0 * 64 + k0], w_hh[m0 * 64 + k0 + 1]);
            ahh[kc][1] = h2pk(w_hh[m1 * 64 + k0], w_hh[m1 * 64 + k0 + 1]);
            ahh[kc][2] = h2pk(w_hh[m0 * 64 + k1], w_hh[m0 * 64 + k1 + 1]);
            ahh[kc][3] = h2pk(w_hh[m1 * 64 + k1], w_hh[m1 * 64 + k1 + 1]);
        }
    }
    const float biasA = b_ih[m0] + b_hh[m0];
    const float biasB = b_ih[m1] + b_hh[m1];

    // combine identities (row-split)
    const bool sideA = (lane < 16);
    const int  myrow = 2 * qid + (sideA ? 0 : 1);
    float cst = 0.f;

    // staging identity (coalesced); decompose k-index sc once
    const int sr = tid >> 6, sc = tid & 63;
    const int xw_u4   = (sc >> 5) * 4 + ((sc >> 1) & 3);              // uint4 idx in slot
    const int xw_comp = (((sc >> 4) & 1) * 2 + ((sc >> 3) & 1)) * 2 + (sc & 1);
    // combine h-write decomposition of `cell`
    const int hw_u4   = (cell >> 5) * 4 + ((cell >> 1) & 3);
    const int hw_comp = (((cell >> 4) & 1) * 2 + ((cell >> 3) & 1)) * 2 + (cell & 1);

    // write fp16 value for k-index (pre-decomposed) into slot S (uint4 base)
    auto putx = [&](int row, int S, float v) {
        reinterpret_cast<__half*>(&bq[row][S + xw_u4])[xw_comp] = __float2half_rn(v);
    };
    auto ldx = [&](int t) -> float {
        return (t < Tn) ? xin[((size_t)t * BnP + b0 + sr) * 64 + sc] : 0.f;
    };

    // ---- zero fragment tile ----
    for (int e = tid; e < 8 * RQ * 4; e += NT)
        reinterpret_cast<uint32_t*>(&bq[0][0])[e] = 0u;
    __syncthreads();
    // stage x(0) -> slot x0 (base 0), x(1) -> slot x1 (base 8)
    putx(sr, 0, ldx(0));
    putx(sr, 8, ldx(1));
    __syncthreads();

    const uint4* myrowq = &bq[gid][qid];

    // xproj(slot parity): W_x · x + bias -> carried cx
    float cx0, cx1, cx2, cx3;
    auto xproj = [&](int slot) {
        float d0 = biasA, d1 = biasA, d2 = biasB, d3 = biasB;
        const int S = 8 * slot;
        const uint4 va = myrowq[S];
        hmma(d0, d1, d2, d3, axh[0][0], axh[0][1], axh[0][2], axh[0][3], va.x, va.y);
        hmma(d0, d1, d2, d3, axh[1][0], axh[1][1], axh[1][2], axh[1][3], va.z, va.w);
        if constexpr (XCH == 4) {
            const uint4 vb = myrowq[S + 4];
            hmma(d0, d1, d2, d3, axh[2][0], axh[2][1], axh[2][2], axh[2][3], vb.x, vb.y);
            hmma(d0, d1, d2, d3, axh[3][0], axh[3][1], axh[3][2], axh[3][3], vb.z, vb.w);
        }
        cx0 = d0; cx1 = d1; cx2 = d2; cx3 = d3;
    };

    xproj(0);   // carried for t=0

    // ---- deep x prefetch pipeline: xna = x(t+2), xnb = x(t+3) ----
    float xna = ldx(2);
    float xnb = ldx(3);

    for (int t = 0; t < Tn; t++) {
        __syncthreads();   // ONE barrier: h(t-1), x slots, h_out(t-1) all ready

        // issue LDG for x(t+4) immediately (consumed 2 iterations from now)
        float xnew = 0.f;
        if (t + 4 < Tn)
            xnew = xin[((size_t)(t + 4) * BnP + b0 + sr) * 64 + sc];

        // ---- coalesced flush of h(t-1) to global (off critical path) ----
        if (t > 0 && sr < nrows) {
            if constexpr (!LAST)
                outs[((size_t)(t - 1) * BnP + b0 + sr) * 64 + sc] =
                    h_out[(t - 1) & 1][sr][sc];
        }

        // ---- critical path: W_h · h(t-1), 2 depth-2 chains, init = cx ----
        float d0 = cx0, d1 = cx1, d2 = cx2, d3 = cx3;   // kc pair 0
        float p0 = 0.f, p1 = 0.f, p2 = 0.f, p3 = 0.f;   // kc pair 1
        const int hS = 16 + 8 * ((t + 1) & 1);
        {
            const uint4 va = myrowq[hS];
            const uint4 vb = myrowq[hS + 4];
            hmma(d0, d1, d2, d3, ahh[0][0], ahh[0][1], ahh[0][2], ahh[0][3], va.x, va.y);
            hmma(p0, p1, p2, p3, ahh[2][0], ahh[2][1], ahh[2][2], ahh[2][3], vb.x, vb.y);
            hmma(d0, d1, d2, d3, ahh[1][0], ahh[1][1], ahh[1][2], ahh[1][3], va.z, va.w);
            hmma(p0, p1, p2, p3, ahh[3][0], ahh[3][1], ahh[3][2], ahh[3][3], vb.z, vb.w);
        }
        d0 += p0; d1 += p1; d2 += p2; d3 += p3;

        // ---- off-path: xproj(t+1) (independent accumulators fill tensor pipe)
        if (t + 1 < Tn) xproj((t + 1) & 1);

        // ---- row-split gate gather: 2 side-selected shfls ----
        const float s1 = __shfl_xor_sync(0xffffffffu, sideA ? d1 : d0, 16);
        const float s2 = __shfl_xor_sync(0xffffffffu, sideA ? d3 : d2, 16);
        const float gi = sideA ? d0 : s1;
        const float gf = sideA ? s1 : d1;
        const float gg = sideA ? d2 : s2;
        const float go = sideA ? s2 : d3;

        // ---- combine: one (cell, row) per lane ----
        const float iv = sigm(gi), fv = sigm(gf), gv = htanh(gg), ov = sigm(go);
        cst = fv * cst + iv * gv;
        const float h = ov * htanh(cst);

        // h(t) -> h slot t&1 (single fp16 store) + f32 staging
        {
            const int hw = 16 + 8 * (t & 1);
            reinterpret_cast<__half*>(&bq[myrow][hw + hw_u4])[hw_comp] = __float2half_rn(h);
            h_out[t & 1][myrow][cell] = h;
        }
        // x(t+2) -> x slot t&1 (data loaded >= 1 full iteration ago: ready)
        if (t + 2 < Tn)
            putx(sr, 8 * (t & 1), xna);

        // shift prefetch pipeline
        xna = xnb;
        xnb = xnew;
    }

    __syncthreads();
    if constexpr (!LAST) {
        if (sr < nrows)
            outs[((size_t)(Tn - 1) * BnP + b0 + sr) * 64 + sc] =
                h_out[(Tn - 1) & 1][sr][sc];
    } else {
        if (tid < nrows * 4) {
            const int r = tid >> 2, o = tid & 3;
            float s = b_fc[o];
#pragma unroll
            for (int k = 0; k < Hn; k++)
                s += h_out[(Tn - 1) & 1][r][k] * w_fc[o * Hn + k];
            out_fc[(b0 + r) * 4 + o] = s;
        }
    }
}

extern "C" void kernel_launch(void* const* d_in, const int* in_sizes, int n_in,
                              void* d_out, int out_size)
{
    const float* x    = (const float*)d_in[0];
    const float* wih0 = (const float*)d_in[1];
    const float* whh0 = (const float*)d_in[2];
    const float* bih0 = (const float*)d_in[3];
    const float* bhh0 = (const float*)d_in[4];
    const float* wih1 = (const float*)d_in[5];
    const float* whh1 = (const float*)d_in[6];
    const float* bih1 = (const float*)d_in[7];
    const float* bhh1 = (const float*)d_in[8];
    const float* wih2 = (const float*)d_in[9];
    const float* whh2 = (const float*)d_in[10];
    const float* bih2 = (const float*)d_in[11];
    const float* bhh2 = (const float*)d_in[12];
    const float* wfc  = (const float*)d_in[13];
    const float* bfc  = (const float*)d_in[14];
    float* out = (float*)d_out;

    transpose_x_k<<<Bn * 8, 256>>>(x);

    dim3 grid(GRID);
    dim3 block(NT);
    lstm_hmma_k<0><<<grid, block>>>(wih0, whh0, bih0, bhh0, nullptr, nullptr, nullptr);
    lstm_hmma_k<1><<<grid, block>>>(wih1, whh1, bih1, bhh1, nullptr, nullptr, nullptr);
    lstm_hmma_k<2><<<grid, block>>>(wih2, whh2, bih2, bhh2, wfc,     bfc,     out);
}